// round 1
// baseline (speedup 1.0000x reference)
#include <cuda_runtime.h>
#include <stdint.h>

// Problem constants (fixed shapes from reference)
#define NB        8
#define NT        32
#define NFRAMES   (NB * NT)          // 256
#define DIMD      32
#define DIMH      32
#define DIMW      32
#define VOX       (DIMD * DIMH * DIMW)  // 32768
#define KCAP      512
#define MAXEV     100
#define NTHREADS  256
#define HASH_SZ   1024
#define HASH_MASK 1023
#define HEMPTY    0xFFFFFFFFu

// status codes
#define ST_UNDEC 0
#define ST_KEPT  1
#define ST_SUPP  2

__global__ __launch_bounds__(NTHREADS)
void event_filter_kernel(const float* __restrict__ in, float* __restrict__ out)
{
    const int frame = blockIdx.x;
    const float* fin  = in  + (size_t)frame * 2 * VOX;
    float*       fout = out + (size_t)frame * 2 * VOX;
    const int tid = threadIdx.x;

    __shared__ unsigned long long skey[KCAP];   // (float_bits << 32) | ~voxel
    __shared__ unsigned int       htab[HASH_SZ];
    __shared__ unsigned char      status[KCAP];
    __shared__ int n_sh;
    __shared__ int changed;
    __shared__ int totKept;

    if (tid == 0) { n_sh = 0; totKept = 0; }
    for (int i = tid; i < HASH_SZ; i += NTHREADS) htab[i] = HEMPTY;
    for (int i = tid; i < KCAP; i += NTHREADS) { skey[i] = 0ULL; status[i] = ST_SUPP; }
    __syncthreads();

    // ---- Phase A: compact nonzero energy voxels (energy channel only) ----
    const float4* e4 = (const float4*)fin;
    for (int i = tid; i < VOX / 4; i += NTHREADS) {
        float4 v = e4[i];
        int base = i * 4;
        float vv[4] = { v.x, v.y, v.z, v.w };
        #pragma unroll
        for (int c = 0; c < 4; c++) {
            if (vv[c] > 0.0f) {
                int p = atomicAdd(&n_sh, 1);
                unsigned int fb  = __float_as_uint(vv[c]);
                unsigned int vox = (unsigned int)(base + c);
                // descending by value, tie -> ascending voxel index (matches lax.top_k)
                skey[p] = ((unsigned long long)fb << 32) | (unsigned int)(~vox);
            }
        }
    }
    __syncthreads();
    const int n = n_sh;   // <= 400 < KCAP always

    if (n == 0) {
        // empty frame passes through unchanged
        const float4* s = (const float4*)fin;
        float4*       d = (float4*)fout;
        for (int i = tid; i < 2 * VOX / 4; i += NTHREADS) d[i] = s[i];
        return;
    }

    // ---- Phase B: bitonic sort of 512 keys, descending ----
    for (int k = 2; k <= KCAP; k <<= 1) {
        for (int j = k >> 1; j > 0; j >>= 1) {
            #pragma unroll
            for (int ii = 0; ii < KCAP / NTHREADS; ii++) {
                int i = tid + ii * NTHREADS;
                int ixj = i ^ j;
                if (ixj > i) {
                    unsigned long long a = skey[i], b = skey[ixj];
                    bool desc = ((i & k) == 0);
                    if (desc ? (a < b) : (a > b)) { skey[i] = b; skey[ixj] = a; }
                }
            }
            __syncthreads();
        }
    }

    // ---- Phase C: hash-insert candidates (voxel -> sorted rank) ----
    for (int r = tid; r < n; r += NTHREADS) {
        unsigned long long key = skey[r];
        unsigned int vox = ~((unsigned int)key);          // exact inverse, < 32768
        unsigned int h = (vox * 2654435761u) >> 22;       // top 10 bits
        unsigned int entry = (vox << 9) | (unsigned int)r;
        while (true) {
            unsigned int prev = atomicCAS(&htab[h], HEMPTY, entry);
            if (prev == HEMPTY) break;
            h = (h + 1) & HASH_MASK;
        }
        status[r] = ST_UNDEC;
    }
    __syncthreads();

    // ---- Phase D: NMS fixpoint rounds (greedy = unique fixpoint) ----
    // Suppression radius dist<2.0 on integer coords == the 26-neighborhood.
    for (int round = 0; round < KCAP; round++) {
        if (tid == 0) changed = 0;
        __syncthreads();

        for (int r = tid; r < n; r += NTHREADS) {
            if (status[r] != ST_UNDEC) continue;
            unsigned long long key = skey[r];
            unsigned int vox = ~((unsigned int)key);
            int z = vox >> 10, y = (vox >> 5) & 31, x = vox & 31;

            bool anyKept = false, allDec = true;
            #pragma unroll
            for (int dz = -1; dz <= 1; dz++)
            #pragma unroll
            for (int dy = -1; dy <= 1; dy++)
            #pragma unroll
            for (int dx = -1; dx <= 1; dx++) {
                if (dz == 0 && dy == 0 && dx == 0) continue;
                int nz = z + dz, ny = y + dy, nx = x + dx;
                if ((unsigned)nz >= 32u || (unsigned)ny >= 32u || (unsigned)nx >= 32u) continue;
                unsigned int nv = ((unsigned)nz << 10) | ((unsigned)ny << 5) | (unsigned)nx;
                unsigned int h = (nv * 2654435761u) >> 22;
                while (true) {
                    unsigned int e = htab[h];
                    if (e == HEMPTY) break;                 // no candidate at that voxel
                    if ((e >> 9) == nv) {
                        int q = (int)(e & 511u);
                        if (q < r) {                        // higher-ranked neighbor
                            unsigned char sq = status[q];
                            if (sq == ST_KEPT) anyKept = true;
                            else if (sq == ST_UNDEC) allDec = false;
                        }
                        break;
                    }
                    h = (h + 1) & HASH_MASK;
                }
            }
            if (anyKept)      { status[r] = ST_SUPP; changed = 1; }
            else if (allDec)  { status[r] = ST_KEPT; changed = 1; }
        }
        __syncthreads();
        if (changed == 0) break;
        __syncthreads();   // all threads observed 'changed' before tid0 resets it
    }

    // ---- Phase E: count kept, apply MAX_EVENTS rank cut ----
    {
        int local = 0;
        for (int r = tid; r < n; r += NTHREADS)
            if (status[r] == ST_KEPT) local++;
        if (local) atomicAdd(&totKept, local);
    }
    __syncthreads();
    const bool cut = (totKept > MAXEV);

    // ---- Phase F: write output = zeros + scatter kept points ----
    {
        float4 z4 = make_float4(0.f, 0.f, 0.f, 0.f);
        float4* d4 = (float4*)fout;
        for (int i = tid; i < 2 * VOX / 4; i += NTHREADS) d4[i] = z4;
    }
    __syncthreads();

    for (int r = tid; r < n; r += NTHREADS) {
        if (status[r] == ST_KEPT && (!cut || r < MAXEV)) {
            unsigned long long key = skey[r];
            unsigned int vox = ~((unsigned int)key);
            float val = __uint_as_float((unsigned int)(key >> 32));
            fout[vox]        = val;               // energy * mask == energy at kept voxel
            fout[VOX + vox]  = fin[VOX + vox];    // magnitude * mask == magnitude there
        }
    }
}

extern "C" void kernel_launch(void* const* d_in, const int* in_sizes, int n_in,
                              void* d_out, int out_size)
{
    (void)in_sizes; (void)n_in; (void)out_size;
    const float* x   = (const float*)d_in[0];
    float*       out = (float*)d_out;
    event_filter_kernel<<<NFRAMES, NTHREADS>>>(x, out);
}